// round 3
// baseline (speedup 1.0000x reference)
#include <cuda_runtime.h>
#include <math.h>

#define NROWS 131072
#define ACT_D 12
#define COND_D 256
#define KCB 256
#define ED 16
#define H1D 512
#define H2D 256
#define IN1 (COND_D + ACT_D)   // 268
#define IN2 (COND_D + ED)      // 272

// ---------------- scratch (static device globals; no allocs) ----------------
__device__ float g_cat1[(size_t)NROWS * IN1];
__device__ float g_h1  [(size_t)NROWS * H1D];
__device__ float g_h2  [(size_t)NROWS * H2D];
__device__ float g_z   [(size_t)NROWS * ED];
__device__ float g_dist[(size_t)KCB * NROWS];   // transposed: [k][n]
__device__ float g_cat2[(size_t)NROWS * IN2];
__device__ float g_d1  [(size_t)NROWS * H2D];
__device__ float g_d2  [(size_t)NROWS * H1D];
__device__ double g_qlat, g_contra, g_recon;
__device__ int    g_counts[KCB];

// ---------------- helpers ----------------
__device__ __forceinline__ unsigned fkey(float x) {
    unsigned u = __float_as_uint(x);
    return (u & 0x80000000u) ? ~u : (u | 0x80000000u);
}
__device__ __forceinline__ float finv(unsigned k) {
    return (k & 0x80000000u) ? __uint_as_float(k & 0x7fffffffu)
                             : __uint_as_float(~k);
}

// ---------------- init ----------------
__global__ void init_kernel(int* counts, double* a, double* b, double* c) {
    int t = threadIdx.x;
    counts[t] = 0;
    if (t == 0) { *a = 0.0; *b = 0.0; *c = 0.0; }
}

// ---------------- concat kernels ----------------
__global__ void concat1_kernel(const float* __restrict__ act,
                               const float* __restrict__ cond,
                               float* __restrict__ o) {
    size_t i = (size_t)blockIdx.x * 256 + threadIdx.x;
    size_t n = i / IN1;
    int    j = (int)(i % IN1);
    o[i] = (j < ACT_D) ? act[n * ACT_D + j] : cond[n * COND_D + (j - ACT_D)];
}
__global__ void cat2cond_kernel(const float* __restrict__ cond,
                                float* __restrict__ cat2) {
    size_t i = (size_t)blockIdx.x * 256 + threadIdx.x;
    size_t n = i >> 8;
    int    j = (int)(i & 255);
    cat2[n * IN2 + ED + j] = cond[i];
}

// ---------------- big SGEMM: C = act(A@B + bias), 128x128x8 tiles ----------------
__global__ __launch_bounds__(256) void sgemm_bias_act(
    const float* __restrict__ A, const float* __restrict__ B,
    const float* __restrict__ bias, float* __restrict__ C,
    int M, int Nn, int Kk, int elu)
{
    __shared__ float As[128][9];
    __shared__ float Bs[8][128];
    int tid = threadIdx.x;
    int col0 = blockIdx.x * 128;
    int row0 = blockIdx.y * 128;
    int tx = tid & 15, ty = tid >> 4;
    float acc[8][8];
#pragma unroll
    for (int i = 0; i < 8; i++)
#pragma unroll
        for (int j = 0; j < 8; j++) acc[i][j] = 0.f;

    for (int k0 = 0; k0 < Kk; k0 += 8) {
#pragma unroll
        for (int l = 0; l < 4; l++) {
            int e = tid + l * 256;
            int m = e >> 3, kk = e & 7;
            int k = k0 + kk;
            As[m][kk] = (k < Kk) ? A[(size_t)(row0 + m) * Kk + k] : 0.f;
        }
#pragma unroll
        for (int l = 0; l < 4; l++) {
            int e = tid + l * 256;
            int kk = e >> 7, n = e & 127;
            int k = k0 + kk;
            Bs[kk][n] = (k < Kk) ? B[(size_t)k * Nn + col0 + n] : 0.f;
        }
        __syncthreads();
#pragma unroll
        for (int kk = 0; kk < 8; kk++) {
            float ra[8], rb[8];
#pragma unroll
            for (int i = 0; i < 8; i++) ra[i] = As[ty * 8 + i][kk];
#pragma unroll
            for (int j = 0; j < 8; j++) rb[j] = Bs[kk][tx * 8 + j];
#pragma unroll
            for (int i = 0; i < 8; i++)
#pragma unroll
                for (int j = 0; j < 8; j++)
                    acc[i][j] = fmaf(ra[i], rb[j], acc[i][j]);
        }
        __syncthreads();
    }
#pragma unroll
    for (int i = 0; i < 8; i++) {
        size_t r = (size_t)(row0 + ty * 8 + i);
#pragma unroll
        for (int j = 0; j < 8; j++) {
            float v = acc[i][j] + bias[col0 + tx * 8 + j];
            if (elu) v = (v > 0.f) ? v : expm1f(v);
            C[r * Nn + col0 + tx * 8 + j] = v;
        }
    }
}

// ---------------- narrow GEMM (N=16 or 12) ----------------
template <int NO, int KK, bool DO_ELU, bool RLOSS>
__global__ __launch_bounds__(128) void ngemm_kernel(
    const float* __restrict__ A, const float* __restrict__ B,
    const float* __restrict__ bias, float* __restrict__ C,
    const float* __restrict__ ref, double* __restrict__ rloss)
{
    __shared__ float Bs[KK][NO];
    __shared__ float As[128][33];
    int tid = threadIdx.x;
    size_t row0 = (size_t)blockIdx.x * 128;
    for (int e = tid; e < KK * NO; e += 128) Bs[e / NO][e % NO] = B[e];
    float acc[NO];
#pragma unroll
    for (int j = 0; j < NO; j++) acc[j] = 0.f;

    for (int k0 = 0; k0 < KK; k0 += 32) {
        __syncthreads();
#pragma unroll
        for (int l = 0; l < 32; l++) {
            int e = tid + l * 128;
            int r = e >> 5, c = e & 31;
            As[r][c] = A[(row0 + r) * KK + k0 + c];
        }
        __syncthreads();
#pragma unroll
        for (int kk = 0; kk < 32; kk++) {
            float a = As[tid][kk];
#pragma unroll
            for (int j = 0; j < NO; j++) acc[j] = fmaf(a, Bs[k0 + kk][j], acc[j]);
        }
    }
    float rl = 0.f;
    size_t r = row0 + tid;
#pragma unroll
    for (int j = 0; j < NO; j++) {
        float v = acc[j] + bias[j];
        if (DO_ELU) v = (v > 0.f) ? v : expm1f(v);
        C[r * NO + j] = v;
        if (RLOSS) { float d = v - ref[r * NO + j]; rl += d * d; }
    }
    if (RLOSS) {
#pragma unroll
        for (int o = 16; o > 0; o >>= 1) rl += __shfl_down_sync(0xffffffffu, rl, o);
        __shared__ float ws[4];
        if ((tid & 31) == 0) ws[tid >> 5] = rl;
        __syncthreads();
        if (tid == 0) atomicAdd(rloss, (double)(ws[0] + ws[1] + ws[2] + ws[3]));
    }
}

// ---------------- quantize: distances, argmax, counts, q-latent, dist^T ----------------
__global__ __launch_bounds__(256) void quantize_kernel(
    const float* __restrict__ z, const float* __restrict__ emb,
    float* __restrict__ out_q, float* __restrict__ out_idx,
    float* __restrict__ cat2, float* __restrict__ dist,
    int* __restrict__ counts, double* __restrict__ qlat)
{
    __shared__ float embn[KCB][ED];
    __shared__ float zt[16][ED + 1];
    __shared__ float rinv[16];
    __shared__ float sd[KCB][17];
    __shared__ int   shist[KCB];
    __shared__ float sq;
    int tid = threadIdx.x;
    size_t row0 = (size_t)blockIdx.x * 16;
    shist[tid] = 0;
    if (tid == 0) sq = 0.f;
    {
        float e[ED], s = 0.f;
#pragma unroll
        for (int j = 0; j < ED; j++) { e[j] = emb[tid * ED + j]; s += e[j] * e[j]; }
        float inv = 1.f / fmaxf(sqrtf(s), 1e-12f);
#pragma unroll
        for (int j = 0; j < ED; j++) embn[tid][j] = e[j] * inv;
    }
    { int r = tid >> 4, j = tid & 15; zt[r][j] = z[(row0 + r) * ED + j]; }
    __syncthreads();
    if (tid < 16) {
        float s = 0.f;
#pragma unroll
        for (int j = 0; j < ED; j++) s += zt[tid][j] * zt[tid][j];
        rinv[tid] = 1.f / fmaxf(sqrtf(s), 1e-12f);
    }
    __syncthreads();
    for (int r = 0; r < 16; r++) {
        float s = 0.f;
#pragma unroll
        for (int j = 0; j < ED; j++) s += zt[r][j] * embn[tid][j];
        sd[tid][r] = s * rinv[r];
    }
    __syncthreads();
    int w = tid >> 5, lane = tid & 31;
    // coalesced transposed write of distances
    for (int c = 0; c < 32; c++) {
        int k = w * 32 + c;
        if (lane < 16) dist[(size_t)k * NROWS + row0 + lane] = sd[k][lane];
    }
    // argmax + quantized outputs: warp w owns rows 2w, 2w+1
    for (int rr = 0; rr < 2; rr++) {
        int r = w * 2 + rr;
        float best = -2.f; int bi = 0;
        for (int kk = lane; kk < KCB; kk += 32) {
            float v = sd[kk][r];
            if (v > best) { best = v; bi = kk; }
        }
#pragma unroll
        for (int o = 16; o > 0; o >>= 1) {
            float ov = __shfl_down_sync(0xffffffffu, best, o);
            int   oi = __shfl_down_sync(0xffffffffu, bi, o);
            if (ov > best || (ov == best && oi < bi)) { best = ov; bi = oi; }
        }
        bi = __shfl_sync(0xffffffffu, bi, 0);
        float dd = 0.f;
        if (lane < ED) {
            float qv = emb[bi * ED + lane];
            float d = qv - zt[r][lane];
            out_q[(row0 + r) * ED + lane] = qv;
            cat2[(row0 + r) * IN2 + lane] = qv;
            dd = d * d;
        }
#pragma unroll
        for (int o = 16; o > 0; o >>= 1) dd += __shfl_down_sync(0xffffffffu, dd, o);
        if (lane == 0) {
            atomicAdd(&sq, dd);
            atomicAdd(&shist[bi], 1);
            out_idx[row0 + r] = (float)bi;
        }
    }
    __syncthreads();
    if (shist[tid]) atomicAdd(&counts[tid], shist[tid]);
    if (tid == 0) atomicAdd(qlat, (double)sq);
}

// ---------------- per-column order statistics + contra loss ----------------
__global__ __launch_bounds__(256) void select_kernel(
    const float* __restrict__ dist, double* __restrict__ contra)
{
    __shared__ unsigned hist[2048];
    __shared__ unsigned s_bin, s_rem;
    __shared__ float rf[256];
    int tid = threadIdx.x;
    const float* col = dist + (size_t)blockIdx.x * NROWS;
    unsigned keys[2];
    const int ranks[2] = {NROWS / 2 - 1, NROWS - 512};  // 65535, 130560

    for (int q = 0; q < 2; q++) {
        unsigned rem = (unsigned)ranks[q];
        // level 0: bits [31:21]
        for (int i = tid; i < 2048; i += 256) hist[i] = 0;
        __syncthreads();
        for (int i = tid; i < NROWS; i += 256)
            atomicAdd(&hist[fkey(col[i]) >> 21], 1u);
        __syncthreads();
        if (tid == 0) {
            unsigned c = 0;
            for (unsigned b = 0; b < 2048; b++) {
                unsigned h = hist[b];
                if (c + h > rem) { s_bin = b; s_rem = rem - c; break; }
                c += h;
            }
        }
        __syncthreads();
        unsigned p0 = s_bin; rem = s_rem;
        __syncthreads();
        // level 1: bits [20:10]
        for (int i = tid; i < 2048; i += 256) hist[i] = 0;
        __syncthreads();
        for (int i = tid; i < NROWS; i += 256) {
            unsigned u = fkey(col[i]);
            if ((u >> 21) == p0) atomicAdd(&hist[(u >> 10) & 2047u], 1u);
        }
        __syncthreads();
        if (tid == 0) {
            unsigned c = 0;
            for (unsigned b = 0; b < 2048; b++) {
                unsigned h = hist[b];
                if (c + h > rem) { s_bin = b; s_rem = rem - c; break; }
                c += h;
            }
        }
        __syncthreads();
        unsigned p1 = (p0 << 11) | s_bin; rem = s_rem;
        __syncthreads();
        // level 2: bits [9:0]
        for (int i = tid; i < 1024; i += 256) hist[i] = 0;
        __syncthreads();
        for (int i = tid; i < NROWS; i += 256) {
            unsigned u = fkey(col[i]);
            if ((u >> 10) == p1) atomicAdd(&hist[u & 1023u], 1u);
        }
        __syncthreads();
        if (tid == 0) {
            unsigned c = 0;
            for (unsigned b = 0; b < 1024; b++) {
                unsigned h = hist[b];
                if (c + h > rem) { s_bin = b; break; }
                c += h;
            }
        }
        __syncthreads();
        keys[q] = (p1 << 10) | s_bin;
        __syncthreads();
    }

    unsigned km = keys[0], kt = keys[1];
    float Tmed = finv(km);
    const float INV_TAU = 1.0f / 0.07f;
    int cgt = 0, clt = 0;
    float sgt = 0.f, sexp = 0.f;
    for (int i = tid; i < NROWS; i += 256) {
        float x = col[i];
        unsigned u = fkey(x);
        if (u > kt) { cgt++; sgt += x; }
        if (u < km) { clt++; sexp += expf((x - Tmed) * INV_TAU); }
    }
    float CGT, SGT, CLT, SEXP;
    rf[tid] = (float)cgt; __syncthreads();
    for (int s = 128; s; s >>= 1) { if (tid < s) rf[tid] += rf[tid + s]; __syncthreads(); }
    CGT = rf[0]; __syncthreads();
    rf[tid] = sgt; __syncthreads();
    for (int s = 128; s; s >>= 1) { if (tid < s) rf[tid] += rf[tid + s]; __syncthreads(); }
    SGT = rf[0]; __syncthreads();
    rf[tid] = (float)clt; __syncthreads();
    for (int s = 128; s; s >>= 1) { if (tid < s) rf[tid] += rf[tid + s]; __syncthreads(); }
    CLT = rf[0]; __syncthreads();
    rf[tid] = sexp; __syncthreads();
    for (int s = 128; s; s >>= 1) { if (tid < s) rf[tid] += rf[tid + s]; __syncthreads(); }
    SEXP = rf[0];

    if (tid == 0) {
        float Ttop = finv(kt);
        float dis_pos = (SGT + (512.0f - CGT) * Ttop) * (1.0f / 512.0f);
        float Sx = SEXP + ((float)(NROWS / 2) - CLT);   // ties at Tmed: exp(0)=1
        float a = dis_pos * INV_TAU, b = Tmed * INV_TAU;
        float m = fmaxf(a, b);
        float lse = m + logf(expf(a - m) + Sx * expf(b - m));
        atomicAdd(contra, (double)(lse - a));
    }
}

// ---------------- finalize scalars ----------------
__global__ void finalize_kernel(const int* __restrict__ counts,
                                const double* __restrict__ qlat,
                                const double* __restrict__ contra,
                                const double* __restrict__ recon,
                                float* __restrict__ out_sc)
{
    __shared__ float rr[256];
    int t = threadIdx.x;
    float p = (float)counts[t] / (float)NROWS;
    rr[t] = p * logf(p + 1e-10f);
    __syncthreads();
    for (int s = 128; s; s >>= 1) { if (t < s) rr[t] += rr[t + s]; __syncthreads(); }
    if (t == 0) {
        float q = (float)(*qlat / ((double)NROWS * ED));
        out_sc[0] = q;              // q_latent_loss
        out_sc[1] = 0.25f * q;      // e_latent_loss = COMMIT * same mean
        out_sc[2] = (float)(*contra / (double)KCB);
        out_sc[3] = expf(-rr[0]);   // perplexity
        out_sc[4] = (float)(*recon / ((double)NROWS * ACT_D));
    }
}

// ---------------- launch ----------------
extern "C" void kernel_launch(void* const* d_in, const int* in_sizes, int n_in,
                              void* d_out, int out_size)
{
    const float* actions    = (const float*)d_in[0];
    const float* conditions = (const float*)d_in[1];
    const float* enc_w1 = (const float*)d_in[2];  const float* enc_b1 = (const float*)d_in[3];
    const float* enc_w2 = (const float*)d_in[4];  const float* enc_b2 = (const float*)d_in[5];
    const float* enc_w3 = (const float*)d_in[6];  const float* enc_b3 = (const float*)d_in[7];
    const float* dec_w1 = (const float*)d_in[8];  const float* dec_b1 = (const float*)d_in[9];
    const float* dec_w2 = (const float*)d_in[10]; const float* dec_b2 = (const float*)d_in[11];
    const float* dec_w3 = (const float*)d_in[12]; const float* dec_b3 = (const float*)d_in[13];
    const float* embedding = (const float*)d_in[14];

    float* out = (float*)d_out;
    float* out_rec = out;                                  // N*12
    float* out_q   = out + (size_t)NROWS * ACT_D;          // N*16
    float* out_idx = out_q + (size_t)NROWS * ED;           // N
    float* out_sc  = out_idx + NROWS;                      // 5 scalars

    float *cat1, *h1, *h2, *z, *dist, *cat2, *d1b, *d2b;
    double *qlat, *contra, *recon; int *counts;
    cudaGetSymbolAddress((void**)&cat1,  g_cat1);
    cudaGetSymbolAddress((void**)&h1,    g_h1);
    cudaGetSymbolAddress((void**)&h2,    g_h2);
    cudaGetSymbolAddress((void**)&z,     g_z);
    cudaGetSymbolAddress((void**)&dist,  g_dist);
    cudaGetSymbolAddress((void**)&cat2,  g_cat2);
    cudaGetSymbolAddress((void**)&d1b,   g_d1);
    cudaGetSymbolAddress((void**)&d2b,   g_d2);
    cudaGetSymbolAddress((void**)&qlat,  g_qlat);
    cudaGetSymbolAddress((void**)&contra,g_contra);
    cudaGetSymbolAddress((void**)&recon, g_recon);
    cudaGetSymbolAddress((void**)&counts,g_counts);

    init_kernel<<<1, 256>>>(counts, qlat, contra, recon);
    concat1_kernel<<<(NROWS * IN1) / 256, 256>>>(actions, conditions, cat1);
    cat2cond_kernel<<<(NROWS * COND_D) / 256, 256>>>(conditions, cat2);

    dim3 g1(H1D / 128, NROWS / 128);
    sgemm_bias_act<<<g1, 256>>>(cat1, enc_w1, enc_b1, h1, NROWS, H1D, IN1, 1);
    dim3 g2(H2D / 128, NROWS / 128);
    sgemm_bias_act<<<g2, 256>>>(h1, enc_w2, enc_b2, h2, NROWS, H2D, H1D, 1);
    ngemm_kernel<ED, H2D, false, false><<<NROWS / 128, 128>>>(h2, enc_w3, enc_b3, z, nullptr, nullptr);

    quantize_kernel<<<NROWS / 16, 256>>>(z, embedding, out_q, out_idx, cat2, dist, counts, qlat);
    select_kernel<<<KCB, 256>>>(dist, contra);

    dim3 g3(H2D / 128, NROWS / 128);
    sgemm_bias_act<<<g3, 256>>>(cat2, dec_w1, dec_b1, d1b, NROWS, H2D, IN2, 1);
    dim3 g4(H1D / 128, NROWS / 128);
    sgemm_bias_act<<<g4, 256>>>(d1b, dec_w2, dec_b2, d2b, NROWS, H1D, H2D, 1);
    ngemm_kernel<ACT_D, H1D, false, true><<<NROWS / 128, 128>>>(d2b, dec_w3, dec_b3, out_rec, actions, recon);

    finalize_kernel<<<1, 256>>>(counts, qlat, contra, recon, out_sc);
}

// round 6
// speedup vs baseline: 2.4203x; 2.4203x over previous
#include <cuda_runtime.h>
#include <cuda_bf16.h>
#include <math.h>
#include <stdint.h>

#define NROWS 131072
#define ACT_D 12
#define COND_D 256
#define KCB 256
#define ED 16
#define H1D 512
#define H2D 256

// K' layouts (3 segments of KP, padded to multiple of 32)
#define KP1 272
#define KT1 832      // enc1 / dec1 inputs  (K=268 / 272)
#define KP2 512
#define KT2 1536     // enc2 input (K=512)
#define KP4 256
#define KT4 768      // dec2 input (K=256)

#define GAP_TAU 2e-3f

// ---------------- scratch (static device globals; no allocs) ----------------
__device__ __nv_bfloat16 g_A1 [(size_t)NROWS * KT1];
__device__ __nv_bfloat16 g_Ah1[(size_t)NROWS * KT2];
__device__ __nv_bfloat16 g_A3 [(size_t)NROWS * KT1];
__device__ __nv_bfloat16 g_Ad1[(size_t)NROWS * KT4];
__device__ __nv_bfloat16 g_B1 [(size_t)H1D * KT1];
__device__ __nv_bfloat16 g_B2 [(size_t)H2D * KT2];
__device__ __nv_bfloat16 g_B3 [(size_t)H2D * KT1];
__device__ __nv_bfloat16 g_B4 [(size_t)H1D * KT4];
__device__ float g_h2  [(size_t)NROWS * H2D];
__device__ float g_z   [(size_t)NROWS * ED];
__device__ float g_dist[(size_t)KCB * NROWS];   // transposed: [k][n]
__device__ float g_d2  [(size_t)NROWS * H1D];
__device__ double g_qlat, g_contra, g_recon;
__device__ int    g_counts[KCB];
__device__ int    g_ncand;
__device__ int    g_cand[NROWS];

// ---------------- helpers ----------------
__device__ __forceinline__ uint32_t smem_u32(const void* p) {
    uint32_t a;
    asm("{ .reg .u64 t; cvta.to.shared.u64 t, %1; cvt.u32.u64 %0, t; }"
        : "=r"(a) : "l"(p));
    return a;
}
__device__ __forceinline__ void cp_async16(uint32_t s, const void* g) {
    asm volatile("cp.async.cg.shared.global [%0], [%1], 16;" :: "r"(s), "l"(g) : "memory");
}
__device__ __forceinline__ void cp_commit() {
    asm volatile("cp.async.commit_group;" ::: "memory");
}
template <int N>
__device__ __forceinline__ void cp_wait() {
    asm volatile("cp.async.wait_group %0;" :: "n"(N) : "memory");
}
__device__ __forceinline__ void ldmx4(uint32_t& r0, uint32_t& r1, uint32_t& r2, uint32_t& r3,
                                      uint32_t addr) {
    asm volatile("ldmatrix.sync.aligned.m8n8.x4.shared.b16 {%0,%1,%2,%3}, [%4];"
                 : "=r"(r0), "=r"(r1), "=r"(r2), "=r"(r3) : "r"(addr));
}
__device__ __forceinline__ void mma16816(float* c, const uint32_t* a, const uint32_t* b) {
    asm volatile("mma.sync.aligned.m16n8k16.row.col.f32.bf16.bf16.f32 "
                 "{%0,%1,%2,%3}, {%4,%5,%6,%7}, {%8,%9}, {%0,%1,%2,%3};"
                 : "+f"(c[0]), "+f"(c[1]), "+f"(c[2]), "+f"(c[3])
                 : "r"(a[0]), "r"(a[1]), "r"(a[2]), "r"(a[3]), "r"(b[0]), "r"(b[1]));
}
__device__ __forceinline__ unsigned fkey(float x) {
    unsigned u = __float_as_uint(x);
    return (u & 0x80000000u) ? ~u : (u | 0x80000000u);
}
__device__ __forceinline__ float finv(unsigned k) {
    return (k & 0x80000000u) ? __uint_as_float(k & 0x7fffffffu)
                             : __uint_as_float(~k);
}

// ---------------- init ----------------
__global__ void init_kernel(int* counts, double* a, double* b, double* c, int* ncand) {
    int t = threadIdx.x;
    counts[t] = 0;
    if (t == 0) { *a = 0.0; *b = 0.0; *c = 0.0; *ncand = 0; }
}

// ---------------- split conversions ----------------
// activations: out[row][KT] = [hi | lo | hi] of concat(a[ad], b[bd]) padded to KP
__global__ void conv_cat_kernel(const float* __restrict__ a, int ad,
                                const float* __restrict__ b, int bd,
                                __nv_bfloat16* __restrict__ o, int KP, int KT)
{
    int pairs = KP >> 1;
    size_t t = (size_t)blockIdx.x * 256 + threadIdx.x;
    size_t row = t / pairs;
    if (row >= NROWS) return;
    int p = (int)(t % pairs);
    int j = p * 2;
    float v0, v1;
    if (j < ad)            { v0 = a[row * ad + j];        v1 = a[row * ad + j + 1]; }
    else if (j < ad + bd)  { v0 = b[row * bd + (j - ad)]; v1 = b[row * bd + (j - ad) + 1]; }
    else                   { v0 = 0.f; v1 = 0.f; }
    __nv_bfloat162 hh, ll;
    hh.x = __float2bfloat16(v0); hh.y = __float2bfloat16(v1);
    ll.x = __float2bfloat16(v0 - __bfloat162float(hh.x));
    ll.y = __float2bfloat16(v1 - __bfloat162float(hh.y));
    __nv_bfloat16* base = o + row * (size_t)KT;
    ((__nv_bfloat162*)(base))[p]            = hh;
    ((__nv_bfloat162*)(base + KP))[p]       = ll;
    ((__nv_bfloat162*)(base + 2 * KP))[p]   = hh;
}
// weights: W[K][Nn] -> o[n][KT] = [hi | hi | lo]
__global__ void conv_w_kernel(const float* __restrict__ W, int K, int Nn,
                              __nv_bfloat16* __restrict__ o, int KP, int KT)
{
    size_t t = (size_t)blockIdx.x * 256 + threadIdx.x;
    if (t >= (size_t)Nn * KT) return;
    int n  = (int)(t / KT);
    int kt = (int)(t % KT);
    int s  = kt < KP ? 0 : (kt < 2 * KP ? 1 : 2);
    int k  = kt - s * KP;
    float v = (k < K) ? W[(size_t)k * Nn + n] : 0.f;
    __nv_bfloat16 h = __float2bfloat16(v);
    __nv_bfloat16 r = (s == 2) ? __float2bfloat16(v - __bfloat162float(h)) : h;
    o[(size_t)n * KT + kt] = r;
}

// ---------------- tensor-core GEMM via mma.sync: 128x128 CTA tile ----------------
#define SROW 80
template <int KT, int OUTM>
__global__ __launch_bounds__(256) void tgemm(
    const __nv_bfloat16* __restrict__ Ap,
    const __nv_bfloat16* __restrict__ Bp,
    const float* __restrict__ bias,
    float* __restrict__ Cf,
    __nv_bfloat16* __restrict__ Cb,
    int Nfull, int KPn, int KTn)
{
    __shared__ __align__(16) uint8_t sAm[2][128 * SROW];
    __shared__ __align__(16) uint8_t sBm[2][128 * SROW];

    const int tid = threadIdx.x;
    const int wid = tid >> 5, lane = tid & 31;
    const int wr = wid >> 2, wc = wid & 3;           // warp 2x4 layout
    const size_t row0 = (size_t)blockIdx.y * 128;
    const int    col0 = blockIdx.x * 128;

    const uint32_t sA0 = smem_u32(sAm[0]);
    const uint32_t sB0 = smem_u32(sBm[0]);

    const int NCH = KT / 32;

    float acc[4][4][4];
#pragma unroll
    for (int i = 0; i < 4; i++)
#pragma unroll
        for (int j = 0; j < 4; j++)
#pragma unroll
            for (int e = 0; e < 4; e++) acc[i][j][e] = 0.f;

    auto load_chunk = [&](int c, int buf) {
        const int kc = c * 32;
#pragma unroll
        for (int l = 0; l < 2; l++) {
            int L = tid + l * 256;
            int row = L >> 2, seg = L & 3;
            cp_async16(sA0 + buf * (128 * SROW) + row * SROW + seg * 16,
                       Ap + (row0 + row) * (size_t)KT + kc + seg * 8);
            cp_async16(sB0 + buf * (128 * SROW) + row * SROW + seg * 16,
                       Bp + (size_t)(col0 + row) * KT + kc + seg * 8);
        }
        cp_commit();
    };

    load_chunk(0, 0);

    for (int c = 0; c < NCH; c++) {
        if (c + 1 < NCH) load_chunk(c + 1, (c + 1) & 1);
        if (c + 1 < NCH) cp_wait<1>(); else cp_wait<0>();
        __syncthreads();

        const uint32_t sa = sA0 + (c & 1) * (128 * SROW);
        const uint32_t sb = sB0 + (c & 1) * (128 * SROW);
        const int g = lane >> 3, lr = lane & 7;

#pragma unroll
        for (int ks = 0; ks < 2; ks++) {
            uint32_t af[4][4];
#pragma unroll
            for (int mt = 0; mt < 4; mt++) {
                int r = wr * 64 + mt * 16 + (g & 1) * 8 + lr;
                uint32_t addr = sa + r * SROW + (ks * 16 + (g >> 1) * 8) * 2;
                ldmx4(af[mt][0], af[mt][1], af[mt][2], af[mt][3], addr);
            }
            uint32_t bf[4][2];
#pragma unroll
            for (int bt = 0; bt < 2; bt++) {
                int r = wc * 32 + bt * 16 + (g >> 1) * 8 + lr;
                uint32_t addr = sb + r * SROW + (ks * 16 + (g & 1) * 8) * 2;
                uint32_t r0, r1, r2, r3;
                ldmx4(r0, r1, r2, r3, addr);
                bf[bt * 2][0] = r0;     bf[bt * 2][1] = r1;
                bf[bt * 2 + 1][0] = r2; bf[bt * 2 + 1][1] = r3;
            }
#pragma unroll
            for (int mt = 0; mt < 4; mt++)
#pragma unroll
                for (int nt = 0; nt < 4; nt++)
                    mma16816(acc[mt][nt], af[mt], bf[nt]);
        }
        __syncthreads();
    }

    // epilogue: bias + ELU (+ split-bf16 re-emit)
#pragma unroll
    for (int mt = 0; mt < 4; mt++) {
        size_t ra = row0 + wr * 64 + mt * 16 + (lane >> 2);
        size_t rb = ra + 8;
#pragma unroll
        for (int nt = 0; nt < 4; nt++) {
            int colg = col0 + wc * 32 + nt * 8 + (lane & 3) * 2;
            float b0 = bias[colg], b1 = bias[colg + 1];
            float v00 = acc[mt][nt][0] + b0, v01 = acc[mt][nt][1] + b1;
            float v10 = acc[mt][nt][2] + b0, v11 = acc[mt][nt][3] + b1;
            v00 = (v00 > 0.f) ? v00 : expm1f(v00);
            v01 = (v01 > 0.f) ? v01 : expm1f(v01);
            v10 = (v10 > 0.f) ? v10 : expm1f(v10);
            v11 = (v11 > 0.f) ? v11 : expm1f(v11);
            if (OUTM == 0) {
                *(float2*)(Cf + ra * (size_t)Nfull + colg) = make_float2(v00, v01);
                *(float2*)(Cf + rb * (size_t)Nfull + colg) = make_float2(v10, v11);
            } else {
                __nv_bfloat162 hh, ll;
                __nv_bfloat16* pa = Cb + ra * (size_t)KTn;
                hh.x = __float2bfloat16(v00); hh.y = __float2bfloat16(v01);
                ll.x = __float2bfloat16(v00 - __bfloat162float(hh.x));
                ll.y = __float2bfloat16(v01 - __bfloat162float(hh.y));
                *(__nv_bfloat162*)(pa + colg)           = hh;
                *(__nv_bfloat162*)(pa + KPn + colg)     = ll;
                *(__nv_bfloat162*)(pa + 2 * KPn + colg) = hh;
                __nv_bfloat16* pb = Cb + rb * (size_t)KTn;
                hh.x = __float2bfloat16(v10); hh.y = __float2bfloat16(v11);
                ll.x = __float2bfloat16(v10 - __bfloat162float(hh.x));
                ll.y = __float2bfloat16(v11 - __bfloat162float(hh.y));
                *(__nv_bfloat162*)(pb + colg)           = hh;
                *(__nv_bfloat162*)(pb + KPn + colg)     = ll;
                *(__nv_bfloat162*)(pb + 2 * KPn + colg) = hh;
            }
        }
    }
}

// ---------------- narrow GEMM (N=16 or 12), fp32 SIMT ----------------
template <int NO, int KK, bool RLOSS>
__global__ __launch_bounds__(128) void ngemm_kernel(
    const float* __restrict__ A, const float* __restrict__ B,
    const float* __restrict__ bias, float* __restrict__ C,
    const float* __restrict__ ref, double* __restrict__ rloss)
{
    __shared__ float Bs[KK][NO];
    __shared__ float As[128][33];
    int tid = threadIdx.x;
    size_t row0 = (size_t)blockIdx.x * 128;
    for (int e = tid; e < KK * NO; e += 128) Bs[e / NO][e % NO] = B[e];
    float acc[NO];
#pragma unroll
    for (int j = 0; j < NO; j++) acc[j] = 0.f;

    for (int k0 = 0; k0 < KK; k0 += 32) {
        __syncthreads();
#pragma unroll
        for (int l = 0; l < 32; l++) {
            int e = tid + l * 128;
            int r = e >> 5, c = e & 31;
            As[r][c] = A[(row0 + r) * KK + k0 + c];
        }
        __syncthreads();
#pragma unroll
        for (int kk = 0; kk < 32; kk++) {
            float a = As[tid][kk];
#pragma unroll
            for (int j = 0; j < NO; j++) acc[j] = fmaf(a, Bs[k0 + kk][j], acc[j]);
        }
    }
    float rl = 0.f;
    size_t r = row0 + tid;
#pragma unroll
    for (int j = 0; j < NO; j++) {
        float v = acc[j] + bias[j];
        C[r * NO + j] = v;
        if (RLOSS) { float d = v - ref[r * NO + j]; rl += d * d; }
    }
    if (RLOSS) {
#pragma unroll
        for (int o = 16; o > 0; o >>= 1) rl += __shfl_down_sync(0xffffffffu, rl, o);
        __shared__ float ws[4];
        if ((tid & 31) == 0) ws[tid >> 5] = rl;
        __syncthreads();
        if (tid == 0) atomicAdd(rloss, (double)(ws[0] + ws[1] + ws[2] + ws[3]));
    }
}

// ---------------- quantize (+ near-tie candidate collection) ----------------
__global__ __launch_bounds__(256) void quantize_kernel(
    const float* __restrict__ z, const float* __restrict__ emb,
    float* __restrict__ out_q, float* __restrict__ out_idx,
    float* __restrict__ dist,
    int* __restrict__ counts, double* __restrict__ qlat,
    int* __restrict__ ncand, int* __restrict__ cand)
{
    __shared__ float embn[KCB][ED];
    __shared__ float zt[16][ED + 1];
    __shared__ float rinv[16];
    __shared__ float sd[KCB][17];
    __shared__ int   shist[KCB];
    __shared__ float sq;
    int tid = threadIdx.x;
    size_t row0 = (size_t)blockIdx.x * 16;
    shist[tid] = 0;
    if (tid == 0) sq = 0.f;
    {
        float e[ED], s = 0.f;
#pragma unroll
        for (int j = 0; j < ED; j++) { e[j] = emb[tid * ED + j]; s += e[j] * e[j]; }
        float inv = 1.f / fmaxf(sqrtf(s), 1e-12f);
#pragma unroll
        for (int j = 0; j < ED; j++) embn[tid][j] = e[j] * inv;
    }
    { int r = tid >> 4, j = tid & 15; zt[r][j] = z[(row0 + r) * ED + j]; }
    __syncthreads();
    if (tid < 16) {
        float s = 0.f;
#pragma unroll
        for (int j = 0; j < ED; j++) s += zt[tid][j] * zt[tid][j];
        rinv[tid] = 1.f / fmaxf(sqrtf(s), 1e-12f);
    }
    __syncthreads();
    for (int r = 0; r < 16; r++) {
        float s = 0.f;
#pragma unroll
        for (int j = 0; j < ED; j++) s += zt[r][j] * embn[tid][j];
        sd[tid][r] = s * rinv[r];
    }
    __syncthreads();
    int w = tid >> 5, lane = tid & 31;
    for (int c = 0; c < 32; c++) {
        int k = w * 32 + c;
        if (lane < 16) dist[(size_t)k * NROWS + row0 + lane] = sd[k][lane];
    }
    for (int rr = 0; rr < 2; rr++) {
        int r = w * 2 + rr;
        float best = -2.f; int bi = 0;
        for (int kk = lane; kk < KCB; kk += 32) {
            float v = sd[kk][r];
            if (v > best) { best = v; bi = kk; }
        }
#pragma unroll
        for (int o = 16; o > 0; o >>= 1) {
            float ov = __shfl_down_sync(0xffffffffu, best, o);
            int   oi = __shfl_down_sync(0xffffffffu, bi, o);
            if (ov > best || (ov == best && oi < bi)) { best = ov; bi = oi; }
        }
        bi   = __shfl_sync(0xffffffffu, bi, 0);
        best = __shfl_sync(0xffffffffu, best, 0);
        // second max (excluding bi) for near-tie detection
        float sec = -2.f;
        for (int kk = lane; kk < KCB; kk += 32)
            if (kk != bi) sec = fmaxf(sec, sd[kk][r]);
#pragma unroll
        for (int o = 16; o > 0; o >>= 1)
            sec = fmaxf(sec, __shfl_down_sync(0xffffffffu, sec, o));
        float dd = 0.f;
        if (lane < ED) {
            float qv = emb[bi * ED + lane];
            float d = qv - zt[r][lane];
            out_q[(row0 + r) * ED + lane] = qv;
            dd = d * d;
        }
#pragma unroll
        for (int o = 16; o > 0; o >>= 1) dd += __shfl_down_sync(0xffffffffu, dd, o);
        if (lane == 0) {
            atomicAdd(&sq, dd);
            atomicAdd(&shist[bi], 1);
            out_idx[row0 + r] = (float)bi;
            if (best - sec < GAP_TAU) {
                int s = atomicAdd(ncand, 1);
                cand[s] = (int)(row0 + r);
            }
        }
    }
    __syncthreads();
    if (shist[tid]) atomicAdd(&counts[tid], shist[tid]);
    if (tid == 0) atomicAdd(qlat, (double)sq);
}

// ---------------- exact fp32 re-check of near-tie rows ----------------
__global__ __launch_bounds__(128) void refine_kernel(
    const float* __restrict__ actions, const float* __restrict__ conditions,
    const float* __restrict__ ew1, const float* __restrict__ eb1,
    const float* __restrict__ ew2, const float* __restrict__ eb2,
    const float* __restrict__ ew3, const float* __restrict__ eb3,
    const float* __restrict__ emb,
    const float* __restrict__ zbf,
    float* __restrict__ out_q, float* __restrict__ out_idx,
    int* __restrict__ counts, double* __restrict__ qlat,
    const int* __restrict__ ncand, const int* __restrict__ cand)
{
    __shared__ float x[272];
    __shared__ float h1s[H1D];
    __shared__ float h2s[H2D];
    __shared__ float zs[ED];
    __shared__ float ds[KCB];
    __shared__ float zinv;
    __shared__ int   newidx;
    int tid = threadIdx.x;
    int n = *ncand;
    for (int ci = blockIdx.x; ci < n; ci += gridDim.x) {
        int row = cand[ci];
        for (int j = tid; j < 268; j += 128)
            x[j] = (j < ACT_D) ? actions[(size_t)row * ACT_D + j]
                               : conditions[(size_t)row * COND_D + (j - ACT_D)];
        __syncthreads();
        for (int c = tid; c < H1D; c += 128) {
            float s = eb1[c];
            for (int k = 0; k < 268; k++) s = fmaf(x[k], ew1[(size_t)k * H1D + c], s);
            h1s[c] = (s > 0.f) ? s : expm1f(s);
        }
        __syncthreads();
        for (int c = tid; c < H2D; c += 128) {
            float s = eb2[c];
            for (int k = 0; k < H1D; k++) s = fmaf(h1s[k], ew2[(size_t)k * H2D + c], s);
            h2s[c] = (s > 0.f) ? s : expm1f(s);
        }
        __syncthreads();
        if (tid < ED) {
            float s = eb3[tid];
            for (int k = 0; k < H2D; k++) s = fmaf(h2s[k], ew3[(size_t)k * ED + tid], s);
            zs[tid] = s;
        }
        __syncthreads();
        if (tid == 0) {
            float s = 0.f;
            for (int j = 0; j < ED; j++) s += zs[j] * zs[j];
            zinv = 1.f / fmaxf(sqrtf(s), 1e-12f);
        }
        __syncthreads();
        for (int c = tid; c < KCB; c += 128) {
            float e[ED], s = 0.f, dot = 0.f;
#pragma unroll
            for (int j = 0; j < ED; j++) { e[j] = emb[c * ED + j]; s += e[j] * e[j]; }
            float inv = 1.f / fmaxf(sqrtf(s), 1e-12f);
#pragma unroll
            for (int j = 0; j < ED; j++) dot += (zs[j] * zinv) * (e[j] * inv);
            ds[c] = dot;
        }
        __syncthreads();
        if (tid == 0) {
            float best = ds[0]; int bi = 0;
            for (int c = 1; c < KCB; c++)
                if (ds[c] > best) { best = ds[c]; bi = c; }
            newidx = bi;
        }
        __syncthreads();
        int oldidx = (int)out_idx[row];
        if (newidx != oldidx) {
            if (tid == 0) {
                out_idx[row] = (float)newidx;
                atomicSub(counts + oldidx, 1);
                atomicAdd(counts + newidx, 1);
                float dq = 0.f;
                for (int j = 0; j < ED; j++) {
                    float zb = zbf[(size_t)row * ED + j];
                    float dn = emb[newidx * ED + j] - zb;
                    float dl = emb[oldidx * ED + j] - zb;
                    dq += dn * dn - dl * dl;
                }
                atomicAdd(qlat, (double)dq);
            }
            if (tid < ED) out_q[(size_t)row * ED + tid] = emb[newidx * ED + tid];
        }
        __syncthreads();
    }
}

// ---------------- per-column order statistics + contra loss (merged passes) ----------------
__global__ __launch_bounds__(256) void select_kernel(
    const float* __restrict__ dist, double* __restrict__ contra)
{
    __shared__ unsigned ha[2048], hb[2048];
    __shared__ unsigned s_bin[2], s_rem[2];
    __shared__ float rf[256];
    int tid = threadIdx.x;
    const float* col = dist + (size_t)blockIdx.x * NROWS;
    const unsigned RA = NROWS / 2 - 1;     // 65535 (median threshold)
    const unsigned RB = NROWS - 512;       // 130560 (top threshold)

    for (int i = tid; i < 2048; i += 256) ha[i] = 0;
    __syncthreads();
    for (int i = tid; i < NROWS; i += 256) atomicAdd(&ha[fkey(col[i]) >> 21], 1u);
    __syncthreads();
    if (tid == 0) {
        unsigned c = 0;
        for (unsigned b = 0; b < 2048; b++) {
            unsigned h = ha[b];
            if (c <= RA && c + h > RA) { s_bin[0] = b; s_rem[0] = RA - c; }
            if (c <= RB && c + h > RB) { s_bin[1] = b; s_rem[1] = RB - c; }
            c += h;
        }
    }
    __syncthreads();
    unsigned p0a = s_bin[0], p0b = s_bin[1];
    unsigned rema = s_rem[0], remb = s_rem[1];
    __syncthreads();

    for (int i = tid; i < 2048; i += 256) { ha[i] = 0; hb[i] = 0; }
    __syncthreads();
    for (int i = tid; i < NROWS; i += 256) {
        unsigned u = fkey(col[i]);
        unsigned t = u >> 21, m = (u >> 10) & 2047u;
        if (t == p0a) atomicAdd(&ha[m], 1u);
        if (t == p0b) atomicAdd(&hb[m], 1u);
    }
    __syncthreads();
    if (tid == 0) { unsigned c = 0; for (unsigned b = 0; b < 2048; b++) { unsigned h = ha[b];
        if (c + h > rema) { s_bin[0] = b; s_rem[0] = rema - c; break; } c += h; } }
    if (tid == 1) { unsigned c = 0; for (unsigned b = 0; b < 2048; b++) { unsigned h = hb[b];
        if (c + h > remb) { s_bin[1] = b; s_rem[1] = remb - c; break; } c += h; } }
    __syncthreads();
    unsigned p1a = (p0a << 11) | s_bin[0], p1b = (p0b << 11) | s_bin[1];
    rema = s_rem[0]; remb = s_rem[1];
    __syncthreads();

    for (int i = tid; i < 1024; i += 256) { ha[i] = 0; hb[i] = 0; }
    __syncthreads();
    for (int i = tid; i < NROWS; i += 256) {
        unsigned u = fkey(col[i]);
        if ((u >> 10) == p1a) atomicAdd(&ha[u & 1023u], 1u);
        if ((u >> 10) == p1b) atomicAdd(&hb[u & 1023u], 1u);
    }
    __syncthreads();
    if (tid == 0) { unsigned c = 0; for (unsigned b = 0; b < 1024; b++) { unsigned h = ha[b];
        if (c + h > rema) { s_bin[0] = b; break; } c += h; } }
    if (tid == 1) { unsigned c = 0; for (unsigned b = 0; b < 1024; b++) { unsigned h = hb[b];
        if (c + h > remb) { s_bin[1] = b; break; } c += h; } }
    __syncthreads();
    unsigned km = (p1a << 10) | s_bin[0];
    unsigned kt = (p1b << 10) | s_bin[1];

    float Tmed = finv(km);
    const float INV_TAU = 1.0f / 0.07f;
    int cgt = 0, clt = 0;
    float sgt = 0.f, sexp = 0.f;
    for (int i = tid; i < NROWS; i += 256) {
        float x = col[i];
        unsigned u = fkey(x);
        if (u > kt) { cgt++; sgt += x; }
        if (u < km) { clt++; sexp += expf((x - Tmed) * INV_TAU); }
    }
    float CGT, SGT, CLT, SEXP;
    rf[tid] = (float)cgt; __syncthreads();
    for (int s = 128; s; s >>= 1) { if (tid < s) rf[tid] += rf[tid + s]; __syncthreads(); }
    CGT = rf[0]; __syncthreads();
    rf[tid] = sgt; __syncthreads();
    for (int s = 128; s; s >>= 1) { if (tid < s) rf[tid] += rf[tid + s]; __syncthreads(); }
    SGT = rf[0]; __syncthreads();
    rf[tid] = (float)clt; __syncthreads();
    for (int s = 128; s; s >>= 1) { if (tid < s) rf[tid] += rf[tid + s]; __syncthreads(); }
    CLT = rf[0]; __syncthreads();
    rf[tid] = sexp; __syncthreads();
    for (int s = 128; s; s >>= 1) { if (tid < s) rf[tid] += rf[tid + s]; __syncthreads(); }
    SEXP = rf[0];

    if (tid == 0) {
        float Ttop = finv(kt);
        float dis_pos = (SGT + (512.0f - CGT) * Ttop) * (1.0f / 512.0f);
        float Sx = SEXP + ((float)(NROWS / 2) - CLT);
        float a = dis_pos * INV_TAU, b = Tmed * INV_TAU;
        float m = fmaxf(a, b);
        float lse = m + logf(expf(a - m) + Sx * expf(b - m));
        atomicAdd(contra, (double)(lse - a));
    }
}

// ---------------- finalize scalars ----------------
__global__ void finalize_kernel(const int* __restrict__ counts,
                                const double* __restrict__ qlat,
                                const double* __restrict__ contra,
                                const double* __restrict__ recon,
                                float* __restrict__ out_sc)
{
    __shared__ float rr[256];
    int t = threadIdx.x;
    float p = (float)counts[t] / (float)NROWS;
    rr[t] = p * logf(p + 1e-10f);
    __syncthreads();
    for (int s = 128; s; s >>= 1) { if (t < s) rr[t] += rr[t + s]; __syncthreads(); }
    if (t == 0) {
        float q = (float)(*qlat / ((double)NROWS * ED));
        out_sc[0] = q;
        out_sc[1] = 0.25f * q;
        out_sc[2] = (float)(*contra / (double)KCB);
        out_sc[3] = expf(-rr[0]);
        out_sc[4] = (float)(*recon / ((double)NROWS * ACT_D));
    }
}

// ---------------- launch ----------------
extern "C" void kernel_launch(void* const* d_in, const int* in_sizes, int n_in,
                              void* d_out, int out_size)
{
    const float* actions    = (const float*)d_in[0];
    const float* conditions = (const float*)d_in[1];
    const float* enc_w1 = (const float*)d_in[2];  const float* enc_b1 = (const float*)d_in[3];
    const float* enc_w2 = (const float*)d_in[4];  const float* enc_b2 = (const float*)d_in[5];
    const float* enc_w3 = (const float*)d_in[6];  const float* enc_b3 = (const float*)d_in[7];
    const float* dec_w1 = (const float*)d_in[8];  const float* dec_b1 = (const float*)d_in[9];
    const float* dec_w2 = (const float*)d_in[10]; const float* dec_b2 = (const float*)d_in[11];
    const float* dec_w3 = (const float*)d_in[12]; const float* dec_b3 = (const float*)d_in[13];
    const float* embedding = (const float*)d_in[14];

    float* out = (float*)d_out;
    float* out_rec = out;
    float* out_q   = out + (size_t)NROWS * ACT_D;
    float* out_idx = out_q + (size_t)NROWS * ED;
    float* out_sc  = out_idx + NROWS;

    __nv_bfloat16 *A1, *Ah1, *A3, *Ad1, *B1, *B2, *B3, *B4;
    float *h2, *z, *dist, *d2;
    double *qlat, *contra, *recon; int *counts, *ncand, *cand;
    cudaGetSymbolAddress((void**)&A1,  g_A1);
    cudaGetSymbolAddress((void**)&Ah1, g_Ah1);
    cudaGetSymbolAddress((void**)&A3,  g_A3);
    cudaGetSymbolAddress((void**)&Ad1, g_Ad1);
    cudaGetSymbolAddress((void**)&B1,  g_B1);
    cudaGetSymbolAddress((void**)&B2,  g_B2);
    cudaGetSymbolAddress((void**)&B3,  g_B3);
    cudaGetSymbolAddress((void**)&B4,  g_B4);
    cudaGetSymbolAddress((void**)&h2,  g_h2);
    cudaGetSymbolAddress((void**)&z,   g_z);
    cudaGetSymbolAddress((void**)&dist,g_dist);
    cudaGetSymbolAddress((void**)&d2,  g_d2);
    cudaGetSymbolAddress((void**)&qlat,  g_qlat);
    cudaGetSymbolAddress((void**)&contra,g_contra);
    cudaGetSymbolAddress((void**)&recon, g_recon);
    cudaGetSymbolAddress((void**)&counts,g_counts);
    cudaGetSymbolAddress((void**)&ncand, g_ncand);
    cudaGetSymbolAddress((void**)&cand,  g_cand);

    init_kernel<<<1, 256>>>(counts, qlat, contra, recon, ncand);

    // weight splits (tiny)
    conv_w_kernel<<<((size_t)H1D * KT1 + 255) / 256, 256>>>(enc_w1, 268, H1D, B1, KP1, KT1);
    conv_w_kernel<<<((size_t)H2D * KT2 + 255) / 256, 256>>>(enc_w2, 512, H2D, B2, KP2, KT2);
    conv_w_kernel<<<((size_t)H2D * KT1 + 255) / 256, 256>>>(dec_w1, 272, H2D, B3, KP1, KT1);
    conv_w_kernel<<<((size_t)H1D * KT4 + 255) / 256, 256>>>(dec_w2, 256, H1D, B4, KP4, KT4);

    // encoder input split
    conv_cat_kernel<<<((size_t)NROWS * (KP1 / 2) + 255) / 256, 256>>>(
        actions, ACT_D, conditions, COND_D, A1, KP1, KT1);

    // enc1: 268 -> 512 (bf16-split out)
    tgemm<KT1, 1><<<dim3(H1D / 128, NROWS / 128), 256>>>(
        A1, B1, enc_b1, nullptr, Ah1, H1D, KP2, KT2);
    // enc2: 512 -> 256 (fp32 out)
    tgemm<KT2, 0><<<dim3(H2D / 128, NROWS / 128), 256>>>(
        Ah1, B2, enc_b2, h2, nullptr, H2D, 0, 0);
    // enc3: 256 -> 16 (fp32 SIMT, no ELU)
    ngemm_kernel<ED, H2D, false><<<NROWS / 128, 128>>>(h2, enc_w3, enc_b3, z, nullptr, nullptr);

    quantize_kernel<<<NROWS / 16, 256>>>(z, embedding, out_q, out_idx, dist, counts, qlat,
                                         ncand, cand);
    // exact fp32 re-check of near-tie rows (fixes argmax flips from bf16 split)
    refine_kernel<<<1024, 128>>>(actions, conditions,
                                 enc_w1, enc_b1, enc_w2, enc_b2, enc_w3, enc_b3,
                                 embedding, z, out_q, out_idx, counts, qlat, ncand, cand);
    select_kernel<<<KCB, 256>>>(dist, contra);

    // decoder input split (quantized ++ conditions) — after refine
    conv_cat_kernel<<<((size_t)NROWS * (KP1 / 2) + 255) / 256, 256>>>(
        out_q, ED, conditions, COND_D, A3, KP1, KT1);

    // dec1: 272 -> 256 (bf16-split out)
    tgemm<KT1, 1><<<dim3(H2D / 128, NROWS / 128), 256>>>(
        A3, B3, dec_b1, nullptr, Ad1, H2D, KP4, KT4);
    // dec2: 256 -> 512 (fp32 out)
    tgemm<KT4, 0><<<dim3(H1D / 128, NROWS / 128), 256>>>(
        Ad1, B4, dec_b2, d2, nullptr, H1D, 0, 0);
    // dec3: 512 -> 12 + reconstruction loss
    ngemm_kernel<ACT_D, H1D, true><<<NROWS / 128, 128>>>(d2, dec_w3, dec_b3, out_rec, actions, recon);

    finalize_kernel<<<1, 256>>>(counts, qlat, contra, recon, out_sc);
}

// round 7
// speedup vs baseline: 2.4961x; 1.0313x over previous
#include <cuda_runtime.h>
#include <cuda_bf16.h>
#include <math.h>
#include <stdint.h>

#define NROWS 131072
#define ACT_D 12
#define COND_D 256
#define KCB 256
#define ED 16
#define H1D 512
#define H2D 256

// 2-segment [hi|lo] layouts; KP = segment length (multiple of 32)
#define KP1 288
#define KA1 576      // enc1 (K=268) / dec1 (K=272) inputs
#define KP2 512
#define KA2 1024     // enc2 input (K=512)
#define KP4 256
#define KA4 512      // dec2 input (K=256)

#define GAP_TAU 2e-3f

// ---------------- scratch (static device globals; no allocs) ----------------
__device__ __nv_bfloat16 g_A1 [(size_t)NROWS * KA1];
__device__ __nv_bfloat16 g_Ah1[(size_t)NROWS * KA2];
__device__ __nv_bfloat16 g_A3 [(size_t)NROWS * KA1];
__device__ __nv_bfloat16 g_Ad1[(size_t)NROWS * KA4];
__device__ __nv_bfloat16 g_B1 [(size_t)H1D * KA1];
__device__ __nv_bfloat16 g_B2 [(size_t)H2D * KA2];
__device__ __nv_bfloat16 g_B3 [(size_t)H2D * KA1];
__device__ __nv_bfloat16 g_B4 [(size_t)H1D * KA4];
__device__ float g_h2  [(size_t)NROWS * H2D];
__device__ float g_z   [(size_t)NROWS * ED];
__device__ float g_dist[(size_t)KCB * NROWS];   // transposed: [k][n]
__device__ float g_d2  [(size_t)NROWS * H1D];
__device__ double g_qlat, g_contra, g_recon;
__device__ int    g_counts[KCB];
__device__ int    g_ncand;
__device__ int    g_cand[NROWS];

// ---------------- helpers ----------------
__device__ __forceinline__ uint32_t smem_u32(const void* p) {
    uint32_t a;
    asm("{ .reg .u64 t; cvta.to.shared.u64 t, %1; cvt.u32.u64 %0, t; }"
        : "=r"(a) : "l"(p));
    return a;
}
__device__ __forceinline__ void cp_async16(uint32_t s, const void* g) {
    asm volatile("cp.async.cg.shared.global [%0], [%1], 16;" :: "r"(s), "l"(g) : "memory");
}
__device__ __forceinline__ void cp_commit() {
    asm volatile("cp.async.commit_group;" ::: "memory");
}
template <int N>
__device__ __forceinline__ void cp_wait() {
    asm volatile("cp.async.wait_group %0;" :: "n"(N) : "memory");
}
__device__ __forceinline__ void ldmx4(uint32_t& r0, uint32_t& r1, uint32_t& r2, uint32_t& r3,
                                      uint32_t addr) {
    asm volatile("ldmatrix.sync.aligned.m8n8.x4.shared.b16 {%0,%1,%2,%3}, [%4];"
                 : "=r"(r0), "=r"(r1), "=r"(r2), "=r"(r3) : "r"(addr));
}
__device__ __forceinline__ void mma16816(float* c, const uint32_t* a, const uint32_t* b) {
    asm volatile("mma.sync.aligned.m16n8k16.row.col.f32.bf16.bf16.f32 "
                 "{%0,%1,%2,%3}, {%4,%5,%6,%7}, {%8,%9}, {%0,%1,%2,%3};"
                 : "+f"(c[0]), "+f"(c[1]), "+f"(c[2]), "+f"(c[3])
                 : "r"(a[0]), "r"(a[1]), "r"(a[2]), "r"(a[3]), "r"(b[0]), "r"(b[1]));
}
__device__ __forceinline__ unsigned fkey(float x) {
    unsigned u = __float_as_uint(x);
    return (u & 0x80000000u) ? ~u : (u | 0x80000000u);
}
__device__ __forceinline__ float finv(unsigned k) {
    return (k & 0x80000000u) ? __uint_as_float(k & 0x7fffffffu)
                             : __uint_as_float(~k);
}

// ---------------- init ----------------
__global__ void init_kernel(int* counts, double* a, double* b, double* c, int* ncand) {
    int t = threadIdx.x;
    counts[t] = 0;
    if (t == 0) { *a = 0.0; *b = 0.0; *c = 0.0; *ncand = 0; }
}

// ---------------- split conversions (2-segment [hi|lo]) ----------------
__global__ void conv_cat_kernel(const float* __restrict__ a, int ad,
                                const float* __restrict__ b, int bd,
                                __nv_bfloat16* __restrict__ o, int KP, int KA)
{
    int pairs = KP >> 1;
    size_t t = (size_t)blockIdx.x * 256 + threadIdx.x;
    size_t row = t / pairs;
    if (row >= NROWS) return;
    int p = (int)(t % pairs);
    int j = p * 2;
    float v0, v1;
    if (j + 1 < ad)        { v0 = a[row * ad + j];        v1 = a[row * ad + j + 1]; }
    else if (j < ad)       { v0 = a[row * ad + j];        v1 = b[row * bd]; }
    else if (j + 1 < ad + bd) { v0 = b[row * bd + (j - ad)]; v1 = b[row * bd + (j - ad) + 1]; }
    else if (j < ad + bd)  { v0 = b[row * bd + (j - ad)]; v1 = 0.f; }
    else                   { v0 = 0.f; v1 = 0.f; }
    __nv_bfloat162 hh, ll;
    hh.x = __float2bfloat16(v0); hh.y = __float2bfloat16(v1);
    ll.x = __float2bfloat16(v0 - __bfloat162float(hh.x));
    ll.y = __float2bfloat16(v1 - __bfloat162float(hh.y));
    __nv_bfloat16* base = o + row * (size_t)KA;
    ((__nv_bfloat162*)(base))[p]      = hh;
    ((__nv_bfloat162*)(base + KP))[p] = ll;
}
// weights: W[K][Nn] -> o[n][KA] = [hi | lo]
__global__ void conv_w_kernel(const float* __restrict__ W, int K, int Nn,
                              __nv_bfloat16* __restrict__ o, int KP, int KA)
{
    size_t t = (size_t)blockIdx.x * 256 + threadIdx.x;
    if (t >= (size_t)Nn * KA) return;
    int n  = (int)(t / KA);
    int kt = (int)(t % KA);
    int s  = kt < KP ? 0 : 1;
    int k  = kt - s * KP;
    float v = (k < K) ? W[(size_t)k * Nn + n] : 0.f;
    __nv_bfloat16 h = __float2bfloat16(v);
    __nv_bfloat16 r = s ? __float2bfloat16(v - __bfloat162float(h)) : h;
    o[(size_t)n * KA + kt] = r;
}

// ---------------- tensor-core GEMM via mma.sync: 128x256 CTA tile ----------------
// 16 warps (2 x 8), each 64x32. K-chunks of 32 over segment KP; per chunk loads
// Ahi/Alo (128x32) and Bhi/Blo (256x32), issues Ahi*Bhi + Alo*Bhi + Ahi*Blo.
// OUTM 0: fp32 output Cf[M][Nfull] (bias+ELU)
// OUTM 1: bf16 [hi|lo] output for next layer, segment KPn (row length 2*KPn)
#define SROW 80
#define S_AHI 0
#define S_ALO 10240
#define S_BHI 20480
#define S_BLO 40960
#define STAGE 61440
#define TG_SMEM (2 * STAGE)

template <int KP, int OUTM>
__global__ __launch_bounds__(512, 1) void tgemm(
    const __nv_bfloat16* __restrict__ Ap,
    const __nv_bfloat16* __restrict__ Bp,
    const float* __restrict__ bias,
    float* __restrict__ Cf,
    __nv_bfloat16* __restrict__ Cb,
    int Nfull, int KPn)
{
    extern __shared__ __align__(16) uint8_t smem[];
    const uint32_t sm = smem_u32(smem);
    const int KA = 2 * KP;

    const int tid = threadIdx.x;
    const int wid = tid >> 5, lane = tid & 31;
    const int wr = wid >> 3, wc = wid & 7;          // warps 2 x 8
    const size_t row0 = (size_t)blockIdx.y * 128;
    const int    col0 = blockIdx.x * 256;

    const int NCH = KP / 32;

    float acc[4][4][4];
#pragma unroll
    for (int i = 0; i < 4; i++)
#pragma unroll
        for (int j = 0; j < 4; j++)
#pragma unroll
            for (int e = 0; e < 4; e++) acc[i][j][e] = 0.f;

    auto load_chunk = [&](int c, int buf) {
        const int kc = c * 32;
        const uint32_t base = sm + buf * STAGE;
        {   // A: 512 lines each of hi/lo
            int row = tid >> 2, seg = tid & 3;
            const __nv_bfloat16* ga = Ap + (row0 + row) * (size_t)KA + kc + seg * 8;
            uint32_t so = row * SROW + seg * 16;
            cp_async16(base + S_AHI + so, ga);
            cp_async16(base + S_ALO + so, ga + KP);
        }
#pragma unroll
        for (int l = 0; l < 2; l++) {   // B: 1024 lines each of hi/lo
            int L = tid + l * 512;
            int row = L >> 2, seg = L & 3;
            const __nv_bfloat16* gb = Bp + (size_t)(col0 + row) * KA + kc + seg * 8;
            uint32_t so = row * SROW + seg * 16;
            cp_async16(base + S_BHI + so, gb);
            cp_async16(base + S_BLO + so, gb + KP);
        }
        cp_commit();
    };

    load_chunk(0, 0);

    for (int c = 0; c < NCH; c++) {
        if (c + 1 < NCH) load_chunk(c + 1, (c + 1) & 1);
        if (c + 1 < NCH) cp_wait<1>(); else cp_wait<0>();
        __syncthreads();

        const uint32_t st = sm + (c & 1) * STAGE;
        const int g = lane >> 3, lr = lane & 7;

#pragma unroll
        for (int ks = 0; ks < 2; ks++) {
            const uint32_t acolo = (ks * 16 + (g >> 1) * 8) * 2;
            const uint32_t bcolo = (ks * 16 + (g & 1) * 8) * 2;
            uint32_t afh[4][4];
#pragma unroll
            for (int mt = 0; mt < 4; mt++) {
                int r = wr * 64 + mt * 16 + (g & 1) * 8 + lr;
                ldmx4(afh[mt][0], afh[mt][1], afh[mt][2], afh[mt][3],
                      st + S_AHI + r * SROW + acolo);
            }
            uint32_t bfh[4][2];
#pragma unroll
            for (int bt = 0; bt < 2; bt++) {
                int r = wc * 32 + bt * 16 + (g >> 1) * 8 + lr;
                uint32_t r0, r1, r2, r3;
                ldmx4(r0, r1, r2, r3, st + S_BHI + r * SROW + bcolo);
                bfh[bt * 2][0] = r0;     bfh[bt * 2][1] = r1;
                bfh[bt * 2 + 1][0] = r2; bfh[bt * 2 + 1][1] = r3;
            }
#pragma unroll
            for (int mt = 0; mt < 4; mt++)
#pragma unroll
                for (int nt = 0; nt < 4; nt++)
                    mma16816(acc[mt][nt], afh[mt], bfh[nt]);
            // A-lo x B-hi
#pragma unroll
            for (int mt = 0; mt < 4; mt++) {
                int r = wr * 64 + mt * 16 + (g & 1) * 8 + lr;
                uint32_t al[4];
                ldmx4(al[0], al[1], al[2], al[3], st + S_ALO + r * SROW + acolo);
#pragma unroll
                for (int nt = 0; nt < 4; nt++)
                    mma16816(acc[mt][nt], al, bfh[nt]);
            }
            // A-hi x B-lo
#pragma unroll
            for (int bt = 0; bt < 2; bt++) {
                int r = wc * 32 + bt * 16 + (g >> 1) * 8 + lr;
                uint32_t r0, r1, r2, r3;
                ldmx4(r0, r1, r2, r3, st + S_BLO + r * SROW + bcolo);
                uint32_t bl0[2] = {r0, r1}, bl1[2] = {r2, r3};
#pragma unroll
                for (int mt = 0; mt < 4; mt++) {
                    mma16816(acc[mt][bt * 2],     afh[mt], bl0);
                    mma16816(acc[mt][bt * 2 + 1], afh[mt], bl1);
                }
            }
        }
        __syncthreads();
    }

    // epilogue: bias + ELU (+ [hi|lo] re-emit)
#pragma unroll
    for (int mt = 0; mt < 4; mt++) {
        size_t ra = row0 + wr * 64 + mt * 16 + (lane >> 2);
        size_t rb = ra + 8;
#pragma unroll
        for (int nt = 0; nt < 4; nt++) {
            int colg = col0 + wc * 32 + nt * 8 + (lane & 3) * 2;
            float b0 = bias[colg], b1 = bias[colg + 1];
            float v00 = acc[mt][nt][0] + b0, v01 = acc[mt][nt][1] + b1;
            float v10 = acc[mt][nt][2] + b0, v11 = acc[mt][nt][3] + b1;
            v00 = (v00 > 0.f) ? v00 : expm1f(v00);
            v01 = (v01 > 0.f) ? v01 : expm1f(v01);
            v10 = (v10 > 0.f) ? v10 : expm1f(v10);
            v11 = (v11 > 0.f) ? v11 : expm1f(v11);
            if (OUTM == 0) {
                *(float2*)(Cf + ra * (size_t)Nfull + colg) = make_float2(v00, v01);
                *(float2*)(Cf + rb * (size_t)Nfull + colg) = make_float2(v10, v11);
            } else {
                const size_t KTn = 2 * (size_t)KPn;
                __nv_bfloat162 hh, ll;
                __nv_bfloat16* pa = Cb + ra * KTn;
                hh.x = __float2bfloat16(v00); hh.y = __float2bfloat16(v01);
                ll.x = __float2bfloat16(v00 - __bfloat162float(hh.x));
                ll.y = __float2bfloat16(v01 - __bfloat162float(hh.y));
                *(__nv_bfloat162*)(pa + colg)       = hh;
                *(__nv_bfloat162*)(pa + KPn + colg) = ll;
                __nv_bfloat16* pb = Cb + rb * KTn;
                hh.x = __float2bfloat16(v10); hh.y = __float2bfloat16(v11);
                ll.x = __float2bfloat16(v10 - __bfloat162float(hh.x));
                ll.y = __float2bfloat16(v11 - __bfloat162float(hh.y));
                *(__nv_bfloat162*)(pb + colg)       = hh;
                *(__nv_bfloat162*)(pb + KPn + colg) = ll;
            }
        }
    }
}

// ---------------- narrow GEMM (N=16 or 12), fp32 SIMT ----------------
template <int NO, int KK, bool RLOSS>
__global__ __launch_bounds__(128) void ngemm_kernel(
    const float* __restrict__ A, const float* __restrict__ B,
    const float* __restrict__ bias, float* __restrict__ C,
    const float* __restrict__ ref, double* __restrict__ rloss)
{
    __shared__ float Bs[KK][NO];
    __shared__ float As[128][33];
    int tid = threadIdx.x;
    size_t row0 = (size_t)blockIdx.x * 128;
    for (int e = tid; e < KK * NO; e += 128) Bs[e / NO][e % NO] = B[e];
    float acc[NO];
#pragma unroll
    for (int j = 0; j < NO; j++) acc[j] = 0.f;

    for (int k0 = 0; k0 < KK; k0 += 32) {
        __syncthreads();
#pragma unroll
        for (int l = 0; l < 32; l++) {
            int e = tid + l * 128;
            int r = e >> 5, c = e & 31;
            As[r][c] = A[(row0 + r) * KK + k0 + c];
        }
        __syncthreads();
#pragma unroll
        for (int kk = 0; kk < 32; kk++) {
            float a = As[tid][kk];
#pragma unroll
            for (int j = 0; j < NO; j++) acc[j] = fmaf(a, Bs[k0 + kk][j], acc[j]);
        }
    }
    float rl = 0.f;
    size_t r = row0 + tid;
#pragma unroll
    for (int j = 0; j < NO; j++) {
        float v = acc[j] + bias[j];
        C[r * NO + j] = v;
        if (RLOSS) { float d = v - ref[r * NO + j]; rl += d * d; }
    }
    if (RLOSS) {
#pragma unroll
        for (int o = 16; o > 0; o >>= 1) rl += __shfl_down_sync(0xffffffffu, rl, o);
        __shared__ float ws[4];
        if ((tid & 31) == 0) ws[tid >> 5] = rl;
        __syncthreads();
        if (tid == 0) atomicAdd(rloss, (double)(ws[0] + ws[1] + ws[2] + ws[3]));
    }
}

// ---------------- quantize (+ near-tie candidate collection) ----------------
__global__ __launch_bounds__(256) void quantize_kernel(
    const float* __restrict__ z, const float* __restrict__ emb,
    float* __restrict__ out_q, float* __restrict__ out_idx,
    float* __restrict__ dist,
    int* __restrict__ counts, double* __restrict__ qlat,
    int* __restrict__ ncand, int* __restrict__ cand)
{
    __shared__ float embn[KCB][ED];
    __shared__ float zt[16][ED + 1];
    __shared__ float rinv[16];
    __shared__ float sd[KCB][17];
    __shared__ int   shist[KCB];
    __shared__ float sq;
    int tid = threadIdx.x;
    size_t row0 = (size_t)blockIdx.x * 16;
    shist[tid] = 0;
    if (tid == 0) sq = 0.f;
    {
        float e[ED], s = 0.f;
#pragma unroll
        for (int j = 0; j < ED; j++) { e[j] = emb[tid * ED + j]; s += e[j] * e[j]; }
        float inv = 1.f / fmaxf(sqrtf(s), 1e-12f);
#pragma unroll
        for (int j = 0; j < ED; j++) embn[tid][j] = e[j] * inv;
    }
    { int r = tid >> 4, j = tid & 15; zt[r][j] = z[(row0 + r) * ED + j]; }
    __syncthreads();
    if (tid < 16) {
        float s = 0.f;
#pragma unroll
        for (int j = 0; j < ED; j++) s += zt[tid][j] * zt[tid][j];
        rinv[tid] = 1.f / fmaxf(sqrtf(s), 1e-12f);
    }
    __syncthreads();
    for (int r = 0; r < 16; r++) {
        float s = 0.f;
#pragma unroll
        for (int j = 0; j < ED; j++) s += zt[r][j] * embn[tid][j];
        sd[tid][r] = s * rinv[r];
    }
    __syncthreads();
    int w = tid >> 5, lane = tid & 31;
    for (int c = 0; c < 32; c++) {
        int k = w * 32 + c;
        if (lane < 16) dist[(size_t)k * NROWS + row0 + lane] = sd[k][lane];
    }
    for (int rr = 0; rr < 2; rr++) {
        int r = w * 2 + rr;
        float best = -2.f; int bi = 0;
        for (int kk = lane; kk < KCB; kk += 32) {
            float v = sd[kk][r];
            if (v > best) { best = v; bi = kk; }
        }
#pragma unroll
        for (int o = 16; o > 0; o >>= 1) {
            float ov = __shfl_down_sync(0xffffffffu, best, o);
            int   oi = __shfl_down_sync(0xffffffffu, bi, o);
            if (ov > best || (ov == best && oi < bi)) { best = ov; bi = oi; }
        }
        bi   = __shfl_sync(0xffffffffu, bi, 0);
        best = __shfl_sync(0xffffffffu, best, 0);
        float sec = -2.f;
        for (int kk = lane; kk < KCB; kk += 32)
            if (kk != bi) sec = fmaxf(sec, sd[kk][r]);
#pragma unroll
        for (int o = 16; o > 0; o >>= 1)
            sec = fmaxf(sec, __shfl_down_sync(0xffffffffu, sec, o));
        float dd = 0.f;
        if (lane < ED) {
            float qv = emb[bi * ED + lane];
            float d = qv - zt[r][lane];
            out_q[(row0 + r) * ED + lane] = qv;
            dd = d * d;
        }
#pragma unroll
        for (int o = 16; o > 0; o >>= 1) dd += __shfl_down_sync(0xffffffffu, dd, o);
        if (lane == 0) {
            atomicAdd(&sq, dd);
            atomicAdd(&shist[bi], 1);
            out_idx[row0 + r] = (float)bi;
            if (best - sec < GAP_TAU) {
                int s = atomicAdd(ncand, 1);
                cand[s] = (int)(row0 + r);
            }
        }
    }
    __syncthreads();
    if (shist[tid]) atomicAdd(&counts[tid], shist[tid]);
    if (tid == 0) atomicAdd(qlat, (double)sq);
}

// ---------------- exact fp32 re-check of near-tie rows ----------------
__global__ __launch_bounds__(128) void refine_kernel(
    const float* __restrict__ actions, const float* __restrict__ conditions,
    const float* __restrict__ ew1, const float* __restrict__ eb1,
    const float* __restrict__ ew2, const float* __restrict__ eb2,
    const float* __restrict__ ew3, const float* __restrict__ eb3,
    const float* __restrict__ emb,
    const float* __restrict__ zbf,
    float* __restrict__ out_q, float* __restrict__ out_idx,
    int* __restrict__ counts, double* __restrict__ qlat,
    const int* __restrict__ ncand, const int* __restrict__ cand)
{
    __shared__ float x[272];
    __shared__ float h1s[H1D];
    __shared__ float h2s[H2D];
    __shared__ float zs[ED];
    __shared__ float ds[KCB];
    __shared__ float zinv;
    __shared__ int   newidx;
    int tid = threadIdx.x;
    int n = *ncand;
    for (int ci = blockIdx.x; ci < n; ci += gridDim.x) {
        int row = cand[ci];
        for (int j = tid; j < 268; j += 128)
            x[j] = (j < ACT_D) ? actions[(size_t)row * ACT_D + j]
                               : conditions[(size_t)row * COND_D + (j - ACT_D)];
        __syncthreads();
        for (int c = tid; c < H1D; c += 128) {
            float s = eb1[c];
            for (int k = 0; k < 268; k++) s = fmaf(x[k], ew1[(size_t)k * H1D + c], s);
            h1s[c] = (s > 0.f) ? s : expm1f(s);
        }
        __syncthreads();
        for (int c = tid; c < H2D; c += 128) {
            float s = eb2[c];
            for (int k = 0; k < H1D; k++) s = fmaf(h1s[k], ew2[(size_t)k * H2D + c], s);
            h2s[c] = (s > 0.f) ? s : expm1f(s);
        }
        __syncthreads();
        if (tid < ED) {
            float s = eb3[tid];
            for (int k = 0; k < H2D; k++) s = fmaf(h2s[k], ew3[(size_t)k * ED + tid], s);
            zs[tid] = s;
        }
        __syncthreads();
        if (tid == 0) {
            float s = 0.f;
            for (int j = 0; j < ED; j++) s += zs[j] * zs[j];
            zinv = 1.f / fmaxf(sqrtf(s), 1e-12f);
        }
        __syncthreads();
        for (int c = tid; c < KCB; c += 128) {
            float e[ED], s = 0.f, dot = 0.f;
#pragma unroll
            for (int j = 0; j < ED; j++) { e[j] = emb[c * ED + j]; s += e[j] * e[j]; }
            float inv = 1.f / fmaxf(sqrtf(s), 1e-12f);
#pragma unroll
            for (int j = 0; j < ED; j++) dot += (zs[j] * zinv) * (e[j] * inv);
            ds[c] = dot;
        }
        __syncthreads();
        if (tid == 0) {
            float best = ds[0]; int bi = 0;
            for (int c = 1; c < KCB; c++)
                if (ds[c] > best) { best = ds[c]; bi = c; }
            newidx = bi;
        }
        __syncthreads();
        int oldidx = (int)out_idx[row];
        if (newidx != oldidx) {
            if (tid == 0) {
                out_idx[row] = (float)newidx;
                atomicSub(counts + oldidx, 1);
                atomicAdd(counts + newidx, 1);
                float dq = 0.f;
                for (int j = 0; j < ED; j++) {
                    float zb = zbf[(size_t)row * ED + j];
                    float dn = emb[newidx * ED + j] - zb;
                    float dl = emb[oldidx * ED + j] - zb;
                    dq += dn * dn - dl * dl;
                }
                atomicAdd(qlat, (double)dq);
            }
            if (tid < ED) out_q[(size_t)row * ED + tid] = emb[newidx * ED + tid];
        }
        __syncthreads();
    }
}

// ---------------- per-column order statistics + contra loss ----------------
__global__ __launch_bounds__(256) void select_kernel(
    const float* __restrict__ dist, double* __restrict__ contra)
{
    __shared__ unsigned ha[2048], hb[2048];
    __shared__ unsigned s_bin[2], s_rem[2];
    __shared__ float rf[256];
    int tid = threadIdx.x;
    const float* col = dist + (size_t)blockIdx.x * NROWS;
    const unsigned RA = NROWS / 2 - 1;
    const unsigned RB = NROWS - 512;

    for (int i = tid; i < 2048; i += 256) ha[i] = 0;
    __syncthreads();
    for (int i = tid; i < NROWS; i += 256) atomicAdd(&ha[fkey(col[i]) >> 21], 1u);
    __syncthreads();
    if (tid == 0) {
        unsigned c = 0;
        for (unsigned b = 0; b < 2048; b++) {
            unsigned h = ha[b];
            if (c <= RA && c + h > RA) { s_bin[0] = b; s_rem[0] = RA - c; }
            if (c <= RB && c + h > RB) { s_bin[1] = b; s_rem[1] = RB - c; }
            c += h;
        }
    }
    __syncthreads();
    unsigned p0a = s_bin[0], p0b = s_bin[1];
    unsigned rema = s_rem[0], remb = s_rem[1];
    __syncthreads();

    for (int i = tid; i < 2048; i += 256) { ha[i] = 0; hb[i] = 0; }
    __syncthreads();
    for (int i = tid; i < NROWS; i += 256) {
        unsigned u = fkey(col[i]);
        unsigned t = u >> 21, m = (u >> 10) & 2047u;
        if (t == p0a) atomicAdd(&ha[m], 1u);
        if (t == p0b) atomicAdd(&hb[m], 1u);
    }
    __syncthreads();
    if (tid == 0) { unsigned c = 0; for (unsigned b = 0; b < 2048; b++) { unsigned h = ha[b];
        if (c + h > rema) { s_bin[0] = b; s_rem[0] = rema - c; break; } c += h; } }
    if (tid == 1) { unsigned c = 0; for (unsigned b = 0; b < 2048; b++) { unsigned h = hb[b];
        if (c + h > remb) { s_bin[1] = b; s_rem[1] = remb - c; break; } c += h; } }
    __syncthreads();
    unsigned p1a = (p0a << 11) | s_bin[0], p1b = (p0b << 11) | s_bin[1];
    rema = s_rem[0]; remb = s_rem[1];
    __syncthreads();

    for (int i = tid; i < 1024; i += 256) { ha[i] = 0; hb[i] = 0; }
    __syncthreads();
    for (int i = tid; i < NROWS; i += 256) {
        unsigned u = fkey(col[i]);
        if ((u >> 10) == p1a) atomicAdd(&ha[u & 1023u], 1u);
        if ((u >> 10) == p1b) atomicAdd(&hb[u & 1023u], 1u);
    }
    __syncthreads();
    if (tid == 0) { unsigned c = 0; for (unsigned b = 0; b < 1024; b++) { unsigned h = ha[b];
        if (c + h > rema) { s_bin[0] = b; break; } c += h; } }
    if (tid == 1) { unsigned c = 0; for (unsigned b = 0; b < 1024; b++) { unsigned h = hb[b];
        if (c + h > remb) { s_bin[1] = b; break; } c += h; } }
    __syncthreads();
    unsigned km = (p1a << 10) | s_bin[0];
    unsigned kt = (p1b << 10) | s_bin[1];

    float Tmed = finv(km);
    const float INV_TAU = 1.0f / 0.07f;
    int cgt = 0, clt = 0;
    float sgt = 0.f, sexp = 0.f;
    for (int i = tid; i < NROWS; i += 256) {
        float x = col[i];
        unsigned u = fkey(x);
        if (u > kt) { cgt++; sgt += x; }
        if (u < km) { clt++; sexp += expf((x - Tmed) * INV_TAU); }
    }
    float CGT, SGT, CLT, SEXP;
    rf[tid] = (float)cgt; __syncthreads();
    for (int s = 128; s; s >>= 1) { if (tid < s) rf[tid] += rf[tid + s]; __syncthreads(); }
    CGT = rf[0]; __syncthreads();
    rf[tid] = sgt; __syncthreads();
    for (int s = 128; s; s >>= 1) { if (tid < s) rf[tid] += rf[tid + s]; __syncthreads(); }
    SGT = rf[0]; __syncthreads();
    rf[tid] = (float)clt; __syncthreads();
    for (int s = 128; s; s >>= 1) { if (tid < s) rf[tid] += rf[tid + s]; __syncthreads(); }
    CLT = rf[0]; __syncthreads();
    rf[tid] = sexp; __syncthreads();
    for (int s = 128; s; s >>= 1) { if (tid < s) rf[tid] += rf[tid + s]; __syncthreads(); }
    SEXP = rf[0];

    if (tid == 0) {
        float Ttop = finv(kt);
        float dis_pos = (SGT + (512.0f - CGT) * Ttop) * (1.0f / 512.0f);
        float Sx = SEXP + ((float)(NROWS / 2) - CLT);
        float a = dis_pos * INV_TAU, b = Tmed * INV_TAU;
        float m = fmaxf(a, b);
        float lse = m + logf(expf(a - m) + Sx * expf(b - m));
        atomicAdd(contra, (double)(lse - a));
    }
}

// ---------------- finalize scalars ----------------
__global__ void finalize_kernel(const int* __restrict__ counts,
                                const double* __restrict__ qlat,
                                const double* __restrict__ contra,
                                const double* __restrict__ recon,
                                float* __restrict__ out_sc)
{
    __shared__ float rr[256];
    int t = threadIdx.x;
    float p = (float)counts[t] / (float)NROWS;
    rr[t] = p * logf(p + 1e-10f);
    __syncthreads();
    for (int s = 128; s; s >>= 1) { if (t < s) rr[t] += rr[t + s]; __syncthreads(); }
    if (t == 0) {
        float q = (float)(*qlat / ((double)NROWS * ED));
        out_sc[0] = q;
        out_sc[1] = 0.25f * q;
        out_sc[2] = (float)(*contra / (double)KCB);
        out_sc[3] = expf(-rr[0]);
        out_sc[4] = (float)(*recon / ((double)NROWS * ACT_D));
    }
}

// ---------------- launch ----------------
extern "C" void kernel_launch(void* const* d_in, const int* in_sizes, int n_in,
                              void* d_out, int out_size)
{
    const float* actions    = (const float*)d_in[0];
    const float* conditions = (const float*)d_in[1];
    const float* enc_w1 = (const float*)d_in[2];  const float* enc_b1 = (const float*)d_in[3];
    const float* enc_w2 = (const float*)d_in[4];  const float* enc_b2 = (const float*)d_in[5];
    const float* enc_w3 = (const float*)d_in[6];  const float* enc_b3 = (const float*)d_in[7];
    const float* dec_w1 = (const float*)d_in[8];  const float* dec_b1 = (const float*)d_in[9];
    const float* dec_w2 = (const float*)d_in[10]; const float* dec_b2 = (const float*)d_in[11];
    const float* dec_w3 = (const float*)d_in[12]; const float* dec_b3 = (const float*)d_in[13];
    const float* embedding = (const float*)d_in[14];

    float* out = (float*)d_out;
    float* out_rec = out;
    float* out_q   = out + (size_t)NROWS * ACT_D;
    float* out_idx = out_q + (size_t)NROWS * ED;
    float* out_sc  = out_idx + NROWS;

    __nv_bfloat16 *A1, *Ah1, *A3, *Ad1, *B1, *B2, *B3, *B4;
    float *h2, *z, *dist, *d2;
    double *qlat, *contra, *recon; int *counts, *ncand, *cand;
    cudaGetSymbolAddress((void**)&A1,  g_A1);
    cudaGetSymbolAddress((void**)&Ah1, g_Ah1);
    cudaGetSymbolAddress((void**)&A3,  g_A3);
    cudaGetSymbolAddress((void**)&Ad1, g_Ad1);
    cudaGetSymbolAddress((void**)&B1,  g_B1);
    cudaGetSymbolAddress((void**)&B2,  g_B2);
    cudaGetSymbolAddress((void**)&B3,  g_B3);
    cudaGetSymbolAddress((void**)&B4,  g_B4);
    cudaGetSymbolAddress((void**)&h2,  g_h2);
    cudaGetSymbolAddress((void**)&z,   g_z);
    cudaGetSymbolAddress((void**)&dist,g_dist);
    cudaGetSymbolAddress((void**)&d2,  g_d2);
    cudaGetSymbolAddress((void**)&qlat,  g_qlat);
    cudaGetSymbolAddress((void**)&contra,g_contra);
    cudaGetSymbolAddress((void**)&recon, g_recon);
    cudaGetSymbolAddress((void**)&counts,g_counts);
    cudaGetSymbolAddress((void**)&ncand, g_ncand);
    cudaGetSymbolAddress((void**)&cand,  g_cand);

    cudaFuncSetAttribute((const void*)tgemm<KP1, 1>, cudaFuncAttributeMaxDynamicSharedMemorySize, TG_SMEM);
    cudaFuncSetAttribute((const void*)tgemm<KP2, 0>, cudaFuncAttributeMaxDynamicSharedMemorySize, TG_SMEM);
    cudaFuncSetAttribute((const void*)tgemm<KP4, 0>, cudaFuncAttributeMaxDynamicSharedMemorySize, TG_SMEM);

    init_kernel<<<1, 256>>>(counts, qlat, contra, recon, ncand);

    // weight splits (tiny)
    conv_w_kernel<<<((size_t)H1D * KA1 + 255) / 256, 256>>>(enc_w1, 268, H1D, B1, KP1, KA1);
    conv_w_kernel<<<((size_t)H2D * KA2 + 255) / 256, 256>>>(enc_w2, 512, H2D, B2, KP2, KA2);
    conv_w_kernel<<<((size_t)H2D * KA1 + 255) / 256, 256>>>(dec_w1, 272, H2D, B3, KP1, KA1);
    conv_w_kernel<<<((size_t)H1D * KA4 + 255) / 256, 256>>>(dec_w2, 256, H1D, B4, KP4, KA4);

    // encoder input split
    conv_cat_kernel<<<((size_t)NROWS * (KP1 / 2) + 255) / 256, 256>>>(
        actions, ACT_D, conditions, COND_D, A1, KP1, KA1);

    // enc1: 268 -> 512 ([hi|lo] out)
    tgemm<KP1, 1><<<dim3(2, NROWS / 128), 512, TG_SMEM>>>(
        A1, B1, enc_b1, nullptr, Ah1, H1D, KP2);
    // enc2: 512 -> 256 (fp32 out)
    tgemm<KP2, 0><<<dim3(1, NROWS / 128), 512, TG_SMEM>>>(
        Ah1, B2, enc_b2, h2, nullptr, H2D, 0);
    // enc3: 256 -> 16 (fp32 SIMT, no ELU)
    ngemm_kernel<ED, H2D, false><<<NROWS / 128, 128>>>(h2, enc_w3, enc_b3, z, nullptr, nullptr);

    quantize_kernel<<<NROWS / 16, 256>>>(z, embedding, out_q, out_idx, dist, counts, qlat,
                                         ncand, cand);
    refine_kernel<<<1024, 128>>>(actions, conditions,
                                 enc_w1, enc_b1, enc_w2, enc_b2, enc_w3, enc_b3,
                                 embedding, z, out_q, out_idx, counts, qlat, ncand, cand);
    select_kernel<<<KCB, 256>>>(dist, contra);

    // decoder input split (quantized ++ conditions) — after refine
    conv_cat_kernel<<<((size_t)NROWS * (KP1 / 2) + 255) / 256, 256>>>(
        out_q, ED, conditions, COND_D, A3, KP1, KA1);

    // dec1: 272 -> 256 ([hi|lo] out)
    tgemm<KP1, 1><<<dim3(1, NROWS / 128), 512, TG_SMEM>>>(
        A3, B3, dec_b1, nullptr, Ad1, H2D, KP4);
    // dec2: 256 -> 512 (fp32 out)
    tgemm<KP4, 0><<<dim3(2, NROWS / 128), 512, TG_SMEM>>>(
        Ad1, B4, dec_b2, d2, nullptr, H1D, 0);
    // dec3: 512 -> 12 + reconstruction loss
    ngemm_kernel<ACT_D, H1D, true><<<NROWS / 128, 128>>>(d2, dec_w3, dec_b3, out_rec, actions, recon);

    finalize_kernel<<<1, 256>>>(counts, qlat, contra, recon, out_sc);
}